// round 9
// baseline (speedup 1.0000x reference)
#include <cuda_runtime.h>

#define NH      32
#define HD      128
#define QLR     1536
#define BSZ     8
#define SEQ     4096
#define NQ      (NH*HD)            // 4096 q columns
#define NSPLIT  32
#define LOG2SPL 5
#define TOKS    (SEQ/NSPLIT)       // 128 tokens per work item
#define NWARP   8                  // warps per attention block
#define NPAIR   (TOKS/(2*NWARP))   // 8 pair-iterations per warp
#define NITEMS  (BSZ*NH*NSPLIT)    // 8192 work items
#define GRID_AT (148*3)            // persistent attention grid (3 blocks/SM)
#define KTILES  64
#define KCHUNK  (QLR/KTILES)       // 24
#define LOG2E   1.4426950408889634f
#define TOKF4   ((size_t)NH * 64)  // float4 stride between consecutive tokens
#define DEPTH   3                  // prefetch depth in token-pairs

// Scratch (device globals: no allocation allowed in kernel_launch)
__device__ float  g_qpart[KTILES][BSZ*NQ];      // split-K GEMM partials (16 MB)
__device__ float  g_q[BSZ*NQ];                  // q = h@W + b (log2e-scaled)
__device__ float  g_pacc[BSZ*NH*NSPLIT*HD];     // split-KV weighted-V partials
__device__ float2 g_pml[BSZ*NH*NSPLIT];         // (max, sumexp) per split (log2 domain)
__device__ int    g_work;                        // work-queue counter
__device__ int    g_done[BSZ*NH];                // per-bh completed-split counters

// ---------------------------------------------------------------------------
// Kernel 1: split-K GEMM, float4 columns. grid (8, KTILES=64), block 128
// ---------------------------------------------------------------------------
__global__ void qgemm_kernel(const float* __restrict__ hq,
                             const float* __restrict__ W) {
    __shared__ float sh[BSZ][KCHUNK];
    const int k0 = blockIdx.y * KCHUNK;
    for (int idx = threadIdx.x; idx < BSZ * KCHUNK; idx += blockDim.x) {
        int b = idx / KCHUNK, k = idx % KCHUNK;
        sh[b][k] = hq[b * QLR + k0 + k];
    }
    __syncthreads();

    const int col4 = blockIdx.x * blockDim.x + threadIdx.x;
    const float4* W4 = (const float4*)W;

    float4 acc[BSZ];
#pragma unroll
    for (int b = 0; b < BSZ; b++) acc[b] = make_float4(0.f, 0.f, 0.f, 0.f);

#pragma unroll 8
    for (int k = 0; k < KCHUNK; k++) {
        float4 w = __ldg(&W4[(size_t)(k0 + k) * (NQ / 4) + col4]);
#pragma unroll
        for (int b = 0; b < BSZ; b++) {
            float s = sh[b][k];
            acc[b].x += w.x * s; acc[b].y += w.y * s;
            acc[b].z += w.z * s; acc[b].w += w.w * s;
        }
    }
#pragma unroll
    for (int b = 0; b < BSZ; b++)
        ((float4*)&g_qpart[blockIdx.y][b * NQ])[col4] = acc[b];
}

// ---------------------------------------------------------------------------
// Kernel 2: reduce split-K partials + bias into g_q (log2e-scaled).
// Also resets the work-queue and completion counters (graph-replay safe).
// ---------------------------------------------------------------------------
__global__ void qreduce_kernel(const float* __restrict__ bq) {
    if (blockIdx.x == 0) {
        if (threadIdx.x == 0) g_work = 0;
        if (threadIdx.x < BSZ * NH) g_done[threadIdx.x] = 0;
    }
    int i = blockIdx.x * blockDim.x + threadIdx.x;   // float4 index
    if (i >= BSZ * NQ / 4) return;
    const float4* b4 = (const float4*)bq;
    float4 s = b4[i & (NQ / 4 - 1)];
#pragma unroll 16
    for (int t = 0; t < KTILES; t++) {
        float4 p = ((const float4*)g_qpart[t])[i];
        s.x += p.x; s.y += p.y; s.z += p.z; s.w += p.w;
    }
    s.x *= LOG2E; s.y *= LOG2E; s.z *= LOG2E; s.w *= LOG2E;
    ((float4*)g_q)[i] = s;
}

// ---------------------------------------------------------------------------
// Kernel 3: persistent split-KV flash attention + fused combine.
// Atomic work queue; warp-per-token-pair with DEPTH=3 ring prefetch.
// The block that finishes the last split of a bh combines all 32 splits
// (reads hit L2) and writes the final output row. No cross-block waiting.
// ---------------------------------------------------------------------------
__global__ void __launch_bounds__(NWARP * 32, 3)
attn_partial_kernel(const float* __restrict__ kv, float* __restrict__ out) {
    __shared__ int    s_item;
    __shared__ int    s_last;
    __shared__ float  s_acc[NWARP][HD];
    __shared__ float  s_m[NWARP], s_l[NWARP];
    __shared__ float2 s_ml[NSPLIT];

    const int warp = threadIdx.x >> 5;
    const int lane = threadIdx.x & 31;
    const float4* kv4 = (const float4*)kv;

    for (;;) {
        if (threadIdx.x == 0) s_item = atomicAdd(&g_work, 1);
        __syncthreads();
        const int item = s_item;
        if (item >= NITEMS) break;

        const int split = item & (NSPLIT - 1);
        const int bh    = item >> LOG2SPL;    // b*NH + h
        const int h     = bh & (NH - 1);
        const int b     = bh >> 5;

        // q fragment (already log2e-scaled): lane holds q[lane*4..+3]
        const float4 q4 = *(const float4*)&g_q[bh * HD + lane * 4];

        float  m = -1e30f, l = 0.0f;
        float4 acc = make_float4(0.f, 0.f, 0.f, 0.f);

        // warp handles token pairs (s, s+1), pair stride 2*NWARP tokens
        const int s0 = split * TOKS + warp * 2;
        size_t base = (((size_t)b * SEQ + s0) * NH + h) * 64;
        const size_t PSTRIDE = (size_t)(2 * NWARP) * TOKF4;

        float4 kb[DEPTH][2], vb[DEPTH][2];
#pragma unroll
        for (int i = 0; i < DEPTH; i++) {
            kb[i][0] = __ldg(&kv4[base + lane]);
            vb[i][0] = __ldg(&kv4[base + 32 + lane]);
            kb[i][1] = __ldg(&kv4[base + TOKF4 + lane]);
            vb[i][1] = __ldg(&kv4[base + TOKF4 + 32 + lane]);
            base += PSTRIDE;
        }

#pragma unroll
        for (int p = 0; p < NPAIR; p++) {
            const int slot = p % DEPTH;
            float4 kc0 = kb[slot][0], vc0 = vb[slot][0];
            float4 kc1 = kb[slot][1], vc1 = vb[slot][1];
            if (p + DEPTH < NPAIR) {
                kb[slot][0] = __ldg(&kv4[base + lane]);
                vb[slot][0] = __ldg(&kv4[base + 32 + lane]);
                kb[slot][1] = __ldg(&kv4[base + TOKF4 + lane]);
                vb[slot][1] = __ldg(&kv4[base + TOKF4 + 32 + lane]);
                base += PSTRIDE;
            }
            float sc0 = kc0.x * q4.x + kc0.y * q4.y + kc0.z * q4.z + kc0.w * q4.w;
            float sc1 = kc1.x * q4.x + kc1.y * q4.y + kc1.z * q4.z + kc1.w * q4.w;
#pragma unroll
            for (int o = 16; o > 0; o >>= 1) {
                sc0 += __shfl_xor_sync(0xffffffffu, sc0, o);
                sc1 += __shfl_xor_sync(0xffffffffu, sc1, o);
            }
            float nm    = fmaxf(m, fmaxf(sc0, sc1));
            float scale = exp2f(m - nm);
            float p0    = exp2f(sc0 - nm);
            float p1    = exp2f(sc1 - nm);
            m = nm;
            l = l * scale + p0 + p1;
            acc.x = acc.x * scale + p0 * vc0.x + p1 * vc1.x;
            acc.y = acc.y * scale + p0 * vc0.y + p1 * vc1.y;
            acc.z = acc.z * scale + p0 * vc0.z + p1 * vc1.z;
            acc.w = acc.w * scale + p0 * vc0.w + p1 * vc1.w;
        }

        // merge the NWARP per-warp partial softmaxes
        s_acc[warp][lane * 4 + 0] = acc.x;
        s_acc[warp][lane * 4 + 1] = acc.y;
        s_acc[warp][lane * 4 + 2] = acc.z;
        s_acc[warp][lane * 4 + 3] = acc.w;
        if (lane == 0) { s_m[warp] = m; s_l[warp] = l; }
        __syncthreads();

        float M = -1e30f;
#pragma unroll
        for (int w = 0; w < NWARP; w++) M = fmaxf(M, s_m[w]);
        float L = 0.0f;
#pragma unroll
        for (int w = 0; w < NWARP; w++) L += exp2f(s_m[w] - M) * s_l[w];

        const int d = threadIdx.x;
        if (d < HD) {
            float a = 0.0f;
#pragma unroll
            for (int w = 0; w < NWARP; w++) a += exp2f(s_m[w] - M) * s_acc[w][d];
            g_pacc[(bh * NSPLIT + split) * HD + d] = a;
        }
        if (threadIdx.x == 0)
            g_pml[bh * NSPLIT + split] = make_float2(M, L);

        // ---- completion protocol: release our partials, count splits ----
        __threadfence();                     // release (all writers fence)
        __syncthreads();
        if (threadIdx.x == 0)
            s_last = (atomicAdd(&g_done[bh], 1) == NSPLIT - 1);
        __syncthreads();

        if (s_last) {
            // we finished the last split of this bh: combine (L2-hot reads)
            __threadfence();                 // acquire
            if (threadIdx.x < NSPLIT)
                s_ml[threadIdx.x] = g_pml[bh * NSPLIT + threadIdx.x];
            __syncthreads();

            if (threadIdx.x < HD) {
                float Mg = -1e30f;
#pragma unroll
                for (int i = 0; i < NSPLIT; i++) Mg = fmaxf(Mg, s_ml[i].x);
                float Lg = 0.0f;
#pragma unroll
                for (int i = 0; i < NSPLIT; i++)
                    Lg += exp2f(s_ml[i].x - Mg) * s_ml[i].y;

                float a = 0.0f;
#pragma unroll 8
                for (int i = 0; i < NSPLIT; i++)
                    a += exp2f(s_ml[i].x - Mg) *
                         __ldg(&g_pacc[(bh * NSPLIT + i) * HD + threadIdx.x]);

                out[bh * HD + threadIdx.x] = a / Lg;
            }
        }
        __syncthreads();   // protect s_item / s_* reuse across items
    }
}

// ---------------------------------------------------------------------------
extern "C" void kernel_launch(void* const* d_in, const int* in_sizes, int n_in,
                              void* d_out, int out_size) {
    const float* hq = (const float*)d_in[0];   // (8, 1536)
    const float* kv = (const float*)d_in[1];   // (8, 4096, 32, 256)
    const float* W  = (const float*)d_in[2];   // (1536, 4096)
    const float* bq = (const float*)d_in[3];   // (4096,)
    float* out = (float*)d_out;                // (8, 4096)

    qgemm_kernel<<<dim3(NQ / 4 / 128, KTILES), 128>>>(hq, W);
    qreduce_kernel<<<(BSZ * NQ / 4 + 255) / 256, 256>>>(bq);
    attn_partial_kernel<<<GRID_AT, NWARP * 32>>>(kv, out);
}

// round 10
// speedup vs baseline: 1.0410x; 1.0410x over previous
#include <cuda_runtime.h>

#define NH      32
#define HD      128
#define QLR     1536
#define BSZ     8
#define SEQ     4096
#define NQ      (NH*HD)            // 4096 q columns
#define NSPLIT  16
#define LOG2SPL 4
#define TOKS    (SEQ/NSPLIT)       // 256 tokens per work item
#define NWARP   8                  // warps per attention block
#define NPAIR   (TOKS/(2*NWARP))   // 16 pair-iterations per warp
#define NITEMS  (BSZ*NH*NSPLIT)    // 4096 work items
#define GRID_AT (148*3)            // persistent attention grid (3 blocks/SM)
#define KTILES  64
#define KCHUNK  (QLR/KTILES)       // 24
#define LOG2E   1.4426950408889634f
#define TOKF4   ((size_t)NH * 64)  // float4 stride between consecutive tokens
#define DEPTH   3                  // prefetch depth in token-pairs

// Scratch (device globals: no allocation allowed in kernel_launch)
__device__ float  g_qpart[KTILES][BSZ*NQ];      // split-K GEMM partials (8 MB)
__device__ float  g_q[BSZ*NQ];                  // q = h@W + b (log2e-scaled)
__device__ float  g_pacc[BSZ*NH*NSPLIT*HD];     // split-KV weighted-V partials
__device__ float2 g_pml[BSZ*NH*NSPLIT];         // (max, sumexp) per split (log2 domain)
__device__ int    g_work;                        // work-queue counter
__device__ int    g_done[BSZ*NH];                // per-bh completed-split counters

// ---------------------------------------------------------------------------
// Kernel 1: split-K GEMM, float4 columns. grid (8, KTILES=64), block 128
// ---------------------------------------------------------------------------
__global__ void qgemm_kernel(const float* __restrict__ hq,
                             const float* __restrict__ W) {
    __shared__ float sh[BSZ][KCHUNK];
    const int k0 = blockIdx.y * KCHUNK;
    for (int idx = threadIdx.x; idx < BSZ * KCHUNK; idx += blockDim.x) {
        int b = idx / KCHUNK, k = idx % KCHUNK;
        sh[b][k] = hq[b * QLR + k0 + k];
    }
    __syncthreads();

    const int col4 = blockIdx.x * blockDim.x + threadIdx.x;
    const float4* W4 = (const float4*)W;

    float4 acc[BSZ];
#pragma unroll
    for (int b = 0; b < BSZ; b++) acc[b] = make_float4(0.f, 0.f, 0.f, 0.f);

#pragma unroll 8
    for (int k = 0; k < KCHUNK; k++) {
        float4 w = __ldg(&W4[(size_t)(k0 + k) * (NQ / 4) + col4]);
#pragma unroll
        for (int b = 0; b < BSZ; b++) {
            float s = sh[b][k];
            acc[b].x += w.x * s; acc[b].y += w.y * s;
            acc[b].z += w.z * s; acc[b].w += w.w * s;
        }
    }
#pragma unroll
    for (int b = 0; b < BSZ; b++)
        ((float4*)&g_qpart[blockIdx.y][b * NQ])[col4] = acc[b];
}

// ---------------------------------------------------------------------------
// Kernel 2: reduce split-K partials + bias into g_q (log2e-scaled).
// Also resets the work-queue and completion counters (graph-replay safe).
// ---------------------------------------------------------------------------
__global__ void qreduce_kernel(const float* __restrict__ bq) {
    if (blockIdx.x == 0) {
        if (threadIdx.x == 0) g_work = 0;
        if (threadIdx.x < BSZ * NH) g_done[threadIdx.x] = 0;
    }
    int i = blockIdx.x * blockDim.x + threadIdx.x;   // float4 index
    if (i >= BSZ * NQ / 4) return;
    const float4* b4 = (const float4*)bq;
    float4 s = b4[i & (NQ / 4 - 1)];
#pragma unroll 16
    for (int t = 0; t < KTILES; t++) {
        float4 p = ((const float4*)g_qpart[t])[i];
        s.x += p.x; s.y += p.y; s.z += p.z; s.w += p.w;
    }
    s.x *= LOG2E; s.y *= LOG2E; s.z *= LOG2E; s.w *= LOG2E;
    ((float4*)g_q)[i] = s;
}

// ---------------------------------------------------------------------------
// Kernel 3: persistent split-KV flash attention + fused combine.
// Atomic work queue; warp-per-token-pair with DEPTH=3 ring prefetch.
// The block that finishes the last split of a bh combines all 16 splits
// (reads hit L2) and writes the final output row. No cross-block waiting.
// ---------------------------------------------------------------------------
__global__ void __launch_bounds__(NWARP * 32, 3)
attn_partial_kernel(const float* __restrict__ kv, float* __restrict__ out) {
    __shared__ int   s_item;
    __shared__ int   s_last;
    __shared__ float s_acc[NWARP][HD];
    __shared__ float s_m[NWARP], s_l[NWARP];

    const int warp = threadIdx.x >> 5;
    const int lane = threadIdx.x & 31;
    const float4* kv4 = (const float4*)kv;

    for (;;) {
        if (threadIdx.x == 0) s_item = atomicAdd(&g_work, 1);
        __syncthreads();
        const int item = s_item;
        if (item >= NITEMS) break;

        const int split = item & (NSPLIT - 1);
        const int bh    = item >> LOG2SPL;    // b*NH + h
        const int h     = bh & (NH - 1);
        const int b     = bh >> 5;

        // q fragment (already log2e-scaled): lane holds q[lane*4..+3]
        const float4 q4 = *(const float4*)&g_q[bh * HD + lane * 4];

        float  m = -1e30f, l = 0.0f;
        float4 acc = make_float4(0.f, 0.f, 0.f, 0.f);

        // warp handles token pairs (s, s+1), pair stride 2*NWARP tokens
        const int s0 = split * TOKS + warp * 2;
        size_t base = (((size_t)b * SEQ + s0) * NH + h) * 64;
        const size_t PSTRIDE = (size_t)(2 * NWARP) * TOKF4;

        float4 kb[DEPTH][2], vb[DEPTH][2];
#pragma unroll
        for (int i = 0; i < DEPTH; i++) {
            kb[i][0] = __ldg(&kv4[base + lane]);
            vb[i][0] = __ldg(&kv4[base + 32 + lane]);
            kb[i][1] = __ldg(&kv4[base + TOKF4 + lane]);
            vb[i][1] = __ldg(&kv4[base + TOKF4 + 32 + lane]);
            base += PSTRIDE;
        }

#pragma unroll
        for (int p = 0; p < NPAIR; p++) {
            const int slot = p % DEPTH;
            float4 kc0 = kb[slot][0], vc0 = vb[slot][0];
            float4 kc1 = kb[slot][1], vc1 = vb[slot][1];
            if (p + DEPTH < NPAIR) {
                kb[slot][0] = __ldg(&kv4[base + lane]);
                vb[slot][0] = __ldg(&kv4[base + 32 + lane]);
                kb[slot][1] = __ldg(&kv4[base + TOKF4 + lane]);
                vb[slot][1] = __ldg(&kv4[base + TOKF4 + 32 + lane]);
                base += PSTRIDE;
            }
            float sc0 = kc0.x * q4.x + kc0.y * q4.y + kc0.z * q4.z + kc0.w * q4.w;
            float sc1 = kc1.x * q4.x + kc1.y * q4.y + kc1.z * q4.z + kc1.w * q4.w;
#pragma unroll
            for (int o = 16; o > 0; o >>= 1) {
                sc0 += __shfl_xor_sync(0xffffffffu, sc0, o);
                sc1 += __shfl_xor_sync(0xffffffffu, sc1, o);
            }
            float nm    = fmaxf(m, fmaxf(sc0, sc1));
            float scale = exp2f(m - nm);
            float p0    = exp2f(sc0 - nm);
            float p1    = exp2f(sc1 - nm);
            m = nm;
            l = l * scale + p0 + p1;
            acc.x = acc.x * scale + p0 * vc0.x + p1 * vc1.x;
            acc.y = acc.y * scale + p0 * vc0.y + p1 * vc1.y;
            acc.z = acc.z * scale + p0 * vc0.z + p1 * vc1.z;
            acc.w = acc.w * scale + p0 * vc0.w + p1 * vc1.w;
        }

        // merge the NWARP per-warp partial softmaxes
        s_acc[warp][lane * 4 + 0] = acc.x;
        s_acc[warp][lane * 4 + 1] = acc.y;
        s_acc[warp][lane * 4 + 2] = acc.z;
        s_acc[warp][lane * 4 + 3] = acc.w;
        if (lane == 0) { s_m[warp] = m; s_l[warp] = l; }
        __syncthreads();

        float M = -1e30f;
#pragma unroll
        for (int w = 0; w < NWARP; w++) M = fmaxf(M, s_m[w]);
        float L = 0.0f;
#pragma unroll
        for (int w = 0; w < NWARP; w++) L += exp2f(s_m[w] - M) * s_l[w];

        const int d = threadIdx.x;
        if (d < HD) {
            float a = 0.0f;
#pragma unroll
            for (int w = 0; w < NWARP; w++) a += exp2f(s_m[w] - M) * s_acc[w][d];
            g_pacc[(bh * NSPLIT + split) * HD + d] = a;
        }
        if (threadIdx.x == 0)
            g_pml[bh * NSPLIT + split] = make_float2(M, L);

        // ---- completion protocol: release our partials, count splits ----
        __threadfence();                     // release (all writers fence)
        __syncthreads();
        if (threadIdx.x == 0)
            s_last = (atomicAdd(&g_done[bh], 1) == NSPLIT - 1);
        __syncthreads();

        if (s_last) {
            // we finished the last split of this bh: combine (L2-hot reads)
            __threadfence();                 // acquire
            if (threadIdx.x < HD) {
                float2 ml[NSPLIT];
#pragma unroll
                for (int i = 0; i < NSPLIT; i++)
                    ml[i] = __ldg(&g_pml[bh * NSPLIT + i]);
                float Mg = -1e30f;
#pragma unroll
                for (int i = 0; i < NSPLIT; i++) Mg = fmaxf(Mg, ml[i].x);
                float Lg = 0.0f;
#pragma unroll
                for (int i = 0; i < NSPLIT; i++)
                    Lg += exp2f(ml[i].x - Mg) * ml[i].y;

                float pa[NSPLIT];
#pragma unroll
                for (int i = 0; i < NSPLIT; i++)
                    pa[i] = __ldg(&g_pacc[(bh * NSPLIT + i) * HD + threadIdx.x]);
                float a = 0.0f;
#pragma unroll
                for (int i = 0; i < NSPLIT; i++)
                    a += exp2f(ml[i].x - Mg) * pa[i];

                out[bh * HD + threadIdx.x] = a / Lg;
            }
        }
        __syncthreads();   // protect s_item / s_* / s_last reuse across items
    }
}

// ---------------------------------------------------------------------------
extern "C" void kernel_launch(void* const* d_in, const int* in_sizes, int n_in,
                              void* d_out, int out_size) {
    const float* hq = (const float*)d_in[0];   // (8, 1536)
    const float* kv = (const float*)d_in[1];   // (8, 4096, 32, 256)
    const float* W  = (const float*)d_in[2];   // (1536, 4096)
    const float* bq = (const float*)d_in[3];   // (4096,)
    float* out = (float*)d_out;                // (8, 4096)

    qgemm_kernel<<<dim3(NQ / 4 / 128, KTILES), 128>>>(hq, W);
    qreduce_kernel<<<(BSZ * NQ / 4 + 255) / 256, 256>>>(bq);
    attn_partial_kernel<<<GRID_AT, NWARP * 32>>>(kv, out);
}

// round 11
// speedup vs baseline: 1.0669x; 1.0249x over previous
#include <cuda_runtime.h>

#define NH      32
#define HD      128
#define QLR     1536
#define BSZ     8
#define SEQ     4096
#define NQ      (NH*HD)            // 4096 q columns
#define NSPLIT  16
#define LOG2SPL 4
#define TOKS    (SEQ/NSPLIT)       // 256 tokens per work item
#define NWARP   8                  // warps per attention block
#define NPAIR   (TOKS/(2*NWARP))   // 16 pair-iterations per warp
#define NITEMS  (BSZ*NH*NSPLIT)    // 4096 work items
#define GRID_AT (148*3)            // persistent attention grid (3 blocks/SM)
#define KTILES  96
#define KCHUNK  (QLR/KTILES)       // 16
#define LOG2E   1.4426950408889634f
#define TOKF4   ((size_t)NH * 64)  // float4 stride between consecutive tokens
#define DEPTH   3                  // prefetch depth in token-pairs

// Scratch (device globals: no allocation allowed in kernel_launch)
__device__ float  g_qpart[KTILES][BSZ*NQ];      // split-K GEMM partials (12 MB)
__device__ float  g_q[BSZ*NQ];                  // q = h@W + b (log2e-scaled)
__device__ float  g_pacc[BSZ*NH*NSPLIT*HD];     // split-KV weighted-V partials
__device__ float2 g_pml[BSZ*NH*NSPLIT];         // (max, sumexp) per split (log2 domain)
__device__ int    g_work;                        // work-queue counter
__device__ int    g_done[BSZ*NH];                // per-bh completed-split counters

// ---------------------------------------------------------------------------
// Kernel 1: split-K GEMM, float4 columns. grid (8, KTILES=96), block 128
// ---------------------------------------------------------------------------
__global__ void qgemm_kernel(const float* __restrict__ hq,
                             const float* __restrict__ W) {
    __shared__ float sh[BSZ][KCHUNK];
    const int k0 = blockIdx.y * KCHUNK;
    for (int idx = threadIdx.x; idx < BSZ * KCHUNK; idx += blockDim.x) {
        int b = idx / KCHUNK, k = idx % KCHUNK;
        sh[b][k] = hq[b * QLR + k0 + k];
    }
    __syncthreads();

    const int col4 = blockIdx.x * blockDim.x + threadIdx.x;
    const float4* W4 = (const float4*)W;

    float4 acc[BSZ];
#pragma unroll
    for (int b = 0; b < BSZ; b++) acc[b] = make_float4(0.f, 0.f, 0.f, 0.f);

#pragma unroll
    for (int k = 0; k < KCHUNK; k++) {
        float4 w = __ldg(&W4[(size_t)(k0 + k) * (NQ / 4) + col4]);
#pragma unroll
        for (int b = 0; b < BSZ; b++) {
            float s = sh[b][k];
            acc[b].x += w.x * s; acc[b].y += w.y * s;
            acc[b].z += w.z * s; acc[b].w += w.w * s;
        }
    }
#pragma unroll
    for (int b = 0; b < BSZ; b++)
        ((float4*)&g_qpart[blockIdx.y][b * NQ])[col4] = acc[b];
}

// ---------------------------------------------------------------------------
// Kernel 2: reduce split-K partials + bias into g_q (log2e-scaled).
// Also resets the work-queue and completion counters (graph-replay safe).
// ---------------------------------------------------------------------------
__global__ void qreduce_kernel(const float* __restrict__ bq) {
    if (blockIdx.x == 0) {
        if (threadIdx.x == 0) g_work = 0;
        if (threadIdx.x < BSZ * NH) g_done[threadIdx.x] = 0;
    }
    int i = blockIdx.x * blockDim.x + threadIdx.x;   // float4 index
    if (i >= BSZ * NQ / 4) return;
    const float4* b4 = (const float4*)bq;
    float4 s = b4[i & (NQ / 4 - 1)];
#pragma unroll 16
    for (int t = 0; t < KTILES; t++) {
        float4 p = ((const float4*)g_qpart[t])[i];
        s.x += p.x; s.y += p.y; s.z += p.z; s.w += p.w;
    }
    s.x *= LOG2E; s.y *= LOG2E; s.z *= LOG2E; s.w *= LOG2E;
    ((float4*)g_q)[i] = s;
}

// ---------------------------------------------------------------------------
// Kernel 3: persistent split-KV flash attention + fused combine.
// Atomic work queue; warp-per-token-pair with DEPTH=3 ring prefetch.
// kv loads use __ldcs (evict-first): each byte is touched exactly once.
// The block that finishes the last split of a bh combines all 16 splits
// (reads hit L2) and writes the final output row. No cross-block waiting.
// ---------------------------------------------------------------------------
__global__ void __launch_bounds__(NWARP * 32, 3)
attn_partial_kernel(const float* __restrict__ kv, float* __restrict__ out) {
    __shared__ int   s_item;
    __shared__ int   s_last;
    __shared__ float s_acc[NWARP][HD];
    __shared__ float s_m[NWARP], s_l[NWARP];

    const int warp = threadIdx.x >> 5;
    const int lane = threadIdx.x & 31;
    const float4* kv4 = (const float4*)kv;

    for (;;) {
        if (threadIdx.x == 0) s_item = atomicAdd(&g_work, 1);
        __syncthreads();
        const int item = s_item;
        if (item >= NITEMS) break;

        const int split = item & (NSPLIT - 1);
        const int bh    = item >> LOG2SPL;    // b*NH + h
        const int h     = bh & (NH - 1);
        const int b     = bh >> 5;

        // q fragment (already log2e-scaled): lane holds q[lane*4..+3]
        const float4 q4 = *(const float4*)&g_q[bh * HD + lane * 4];

        float  m = -1e30f, l = 0.0f;
        float4 acc = make_float4(0.f, 0.f, 0.f, 0.f);

        // warp handles token pairs (s, s+1), pair stride 2*NWARP tokens
        const int s0 = split * TOKS + warp * 2;
        size_t base = (((size_t)b * SEQ + s0) * NH + h) * 64;
        const size_t PSTRIDE = (size_t)(2 * NWARP) * TOKF4;

        float4 kb[DEPTH][2], vb[DEPTH][2];
#pragma unroll
        for (int i = 0; i < DEPTH; i++) {
            kb[i][0] = __ldcs(&kv4[base + lane]);
            vb[i][0] = __ldcs(&kv4[base + 32 + lane]);
            kb[i][1] = __ldcs(&kv4[base + TOKF4 + lane]);
            vb[i][1] = __ldcs(&kv4[base + TOKF4 + 32 + lane]);
            base += PSTRIDE;
        }

#pragma unroll
        for (int p = 0; p < NPAIR; p++) {
            const int slot = p % DEPTH;
            float4 kc0 = kb[slot][0], vc0 = vb[slot][0];
            float4 kc1 = kb[slot][1], vc1 = vb[slot][1];
            if (p + DEPTH < NPAIR) {
                kb[slot][0] = __ldcs(&kv4[base + lane]);
                vb[slot][0] = __ldcs(&kv4[base + 32 + lane]);
                kb[slot][1] = __ldcs(&kv4[base + TOKF4 + lane]);
                vb[slot][1] = __ldcs(&kv4[base + TOKF4 + 32 + lane]);
                base += PSTRIDE;
            }
            float sc0 = kc0.x * q4.x + kc0.y * q4.y + kc0.z * q4.z + kc0.w * q4.w;
            float sc1 = kc1.x * q4.x + kc1.y * q4.y + kc1.z * q4.z + kc1.w * q4.w;
#pragma unroll
            for (int o = 16; o > 0; o >>= 1) {
                sc0 += __shfl_xor_sync(0xffffffffu, sc0, o);
                sc1 += __shfl_xor_sync(0xffffffffu, sc1, o);
            }
            float nm    = fmaxf(m, fmaxf(sc0, sc1));
            float scale = exp2f(m - nm);
            float p0    = exp2f(sc0 - nm);
            float p1    = exp2f(sc1 - nm);
            m = nm;
            l = l * scale + p0 + p1;
            acc.x = acc.x * scale + p0 * vc0.x + p1 * vc1.x;
            acc.y = acc.y * scale + p0 * vc0.y + p1 * vc1.y;
            acc.z = acc.z * scale + p0 * vc0.z + p1 * vc1.z;
            acc.w = acc.w * scale + p0 * vc0.w + p1 * vc1.w;
        }

        // merge the NWARP per-warp partial softmaxes
        s_acc[warp][lane * 4 + 0] = acc.x;
        s_acc[warp][lane * 4 + 1] = acc.y;
        s_acc[warp][lane * 4 + 2] = acc.z;
        s_acc[warp][lane * 4 + 3] = acc.w;
        if (lane == 0) { s_m[warp] = m; s_l[warp] = l; }
        __syncthreads();

        float M = -1e30f;
#pragma unroll
        for (int w = 0; w < NWARP; w++) M = fmaxf(M, s_m[w]);
        float L = 0.0f;
#pragma unroll
        for (int w = 0; w < NWARP; w++) L += exp2f(s_m[w] - M) * s_l[w];

        const int d = threadIdx.x;
        if (d < HD) {
            float a = 0.0f;
#pragma unroll
            for (int w = 0; w < NWARP; w++) a += exp2f(s_m[w] - M) * s_acc[w][d];
            g_pacc[(bh * NSPLIT + split) * HD + d] = a;
        }
        if (threadIdx.x == 0)
            g_pml[bh * NSPLIT + split] = make_float2(M, L);

        // ---- completion protocol: release our partials, count splits ----
        __threadfence();                     // release (all writers fence)
        __syncthreads();
        if (threadIdx.x == 0)
            s_last = (atomicAdd(&g_done[bh], 1) == NSPLIT - 1);
        __syncthreads();

        if (s_last) {
            // we finished the last split of this bh: combine (L2-hot reads)
            __threadfence();                 // acquire
            if (threadIdx.x < HD) {
                float2 ml[NSPLIT];
#pragma unroll
                for (int i = 0; i < NSPLIT; i++)
                    ml[i] = __ldg(&g_pml[bh * NSPLIT + i]);
                float Mg = -1e30f;
#pragma unroll
                for (int i = 0; i < NSPLIT; i++) Mg = fmaxf(Mg, ml[i].x);
                float Lg = 0.0f;
#pragma unroll
                for (int i = 0; i < NSPLIT; i++)
                    Lg += exp2f(ml[i].x - Mg) * ml[i].y;

                float pa[NSPLIT];
#pragma unroll
                for (int i = 0; i < NSPLIT; i++)
                    pa[i] = __ldg(&g_pacc[(bh * NSPLIT + i) * HD + threadIdx.x]);
                float a = 0.0f;
#pragma unroll
                for (int i = 0; i < NSPLIT; i++)
                    a += exp2f(ml[i].x - Mg) * pa[i];

                out[bh * HD + threadIdx.x] = a / Lg;
            }
        }
        __syncthreads();   // protect s_item / s_* / s_last reuse across items
    }
}

// ---------------------------------------------------------------------------
extern "C" void kernel_launch(void* const* d_in, const int* in_sizes, int n_in,
                              void* d_out, int out_size) {
    const float* hq = (const float*)d_in[0];   // (8, 1536)
    const float* kv = (const float*)d_in[1];   // (8, 4096, 32, 256)
    const float* W  = (const float*)d_in[2];   // (1536, 4096)
    const float* bq = (const float*)d_in[3];   // (4096,)
    float* out = (float*)d_out;                // (8, 4096)

    qgemm_kernel<<<dim3(NQ / 4 / 128, KTILES), 128>>>(hq, W);
    qreduce_kernel<<<(BSZ * NQ / 4 + 255) / 256, 256>>>(bq);
    attn_partial_kernel<<<GRID_AT, NWARP * 32>>>(kv, out);
}

// round 13
// speedup vs baseline: 1.0770x; 1.0094x over previous
#include <cuda_runtime.h>

#define NH      32
#define HD      128
#define QLR     1536
#define BSZ     8
#define SEQ     4096
#define NQ      (NH*HD)            // 4096 q columns
#define NBH     (BSZ*NH)           // 256 bh rows
#define NSPLIT  16
#define LOG2SPL 4
#define TOKS    (SEQ/NSPLIT)       // 256 tokens per work item
#define NWARP   8                  // warps per attention block
#define NPAIR   (TOKS/(2*NWARP))   // 16 pair-iterations per warp
#define NITEMS  (NBH*NSPLIT)       // 4096 attention work items
#define NITEMS_TOT (NBH + NITEMS)  // + 256 q-reduce items at queue head
#define GRID_AT (148*3)            // persistent attention grid (3 blocks/SM)
#define KTILES  96
#define KCHUNK  (QLR/KTILES)       // 16
#define LOG2E   1.4426950408889634f
#define TOKF4   ((size_t)NH * 64)  // float4 stride between consecutive tokens
#define DEPTH   3                  // prefetch depth in token-pairs

// Scratch (device globals: no allocation allowed in kernel_launch)
__device__ float  g_qpart[KTILES][BSZ*NQ];      // split-K GEMM partials (12 MB)
__device__ float  g_q[BSZ*NQ];                  // q = h@W + b (log2e-scaled)
__device__ float  g_pacc[NBH*NSPLIT*HD];        // split-KV weighted-V partials
__device__ float2 g_pml[NBH*NSPLIT];            // (max, sumexp) per split (log2 domain)
__device__ int    g_work;                        // work-queue counter
__device__ int    g_done[NBH];                   // per-bh completed-split counters
__device__ int    g_qready[NBH];                 // per-bh q-row readiness flags

// ---------------------------------------------------------------------------
// Kernel 1: split-K GEMM, float4 columns. grid (8, KTILES=96), block 128.
// Block (0,0) also resets the attention kernel's counters/flags — visible
// at the kernel boundary before the attention kernel starts.
// ---------------------------------------------------------------------------
__global__ void qgemm_kernel(const float* __restrict__ hq,
                             const float* __restrict__ W) {
    if (blockIdx.x == 0 && blockIdx.y == 0) {
        if (threadIdx.x == 0) g_work = 0;
        if (threadIdx.x < 128) {
            g_done[threadIdx.x]          = 0;
            g_done[threadIdx.x + 128]    = 0;
            g_qready[threadIdx.x]        = 0;
            g_qready[threadIdx.x + 128]  = 0;
        }
    }

    __shared__ float sh[BSZ][KCHUNK];
    const int k0 = blockIdx.y * KCHUNK;
    for (int idx = threadIdx.x; idx < BSZ * KCHUNK; idx += blockDim.x) {
        int b = idx / KCHUNK, k = idx % KCHUNK;
        sh[b][k] = hq[b * QLR + k0 + k];
    }
    __syncthreads();

    const int col4 = blockIdx.x * blockDim.x + threadIdx.x;
    const float4* W4 = (const float4*)W;

    float4 acc[BSZ];
#pragma unroll
    for (int b = 0; b < BSZ; b++) acc[b] = make_float4(0.f, 0.f, 0.f, 0.f);

#pragma unroll
    for (int k = 0; k < KCHUNK; k++) {
        float4 w = __ldg(&W4[(size_t)(k0 + k) * (NQ / 4) + col4]);
#pragma unroll
        for (int b = 0; b < BSZ; b++) {
            float s = sh[b][k];
            acc[b].x += w.x * s; acc[b].y += w.y * s;
            acc[b].z += w.z * s; acc[b].w += w.w * s;
        }
    }
#pragma unroll
    for (int b = 0; b < BSZ; b++)
        ((float4*)&g_qpart[blockIdx.y][b * NQ])[col4] = acc[b];
}

// ---------------------------------------------------------------------------
// Kernel 2: persistent kernel — q-reduce items (queue head) + split-KV flash
// attention + fused combine.
//   item <  NBH           : reduce split-K partials for bh row `item`,
//                           add bias, scale by log2e, publish g_qready[bh].
//   item >= NBH           : attention split item; spins (bounded — producer
//                           block is resident) until its bh's q row is ready.
// ---------------------------------------------------------------------------
__global__ void __launch_bounds__(NWARP * 32, 3)
attn_partial_kernel(const float* __restrict__ kv,
                    const float* __restrict__ bq,
                    float* __restrict__ out) {
    __shared__ int   s_item;
    __shared__ int   s_last;
    __shared__ float s_acc[NWARP][HD];
    __shared__ float s_m[NWARP], s_l[NWARP];

    const int warp = threadIdx.x >> 5;
    const int lane = threadIdx.x & 31;
    const float4* kv4 = (const float4*)kv;

    for (;;) {
        if (threadIdx.x == 0) s_item = atomicAdd(&g_work, 1);
        __syncthreads();
        const int item = s_item;
        if (item >= NITEMS_TOT) break;

        // ---------------- q-reduce item ----------------
        if (item < NBH) {
            const int bh = item;
            // 32 float4 per q row; threads 0..31 each own one float4.
            if (threadIdx.x < HD / 4) {
                const int i = bh * (HD / 4) + threadIdx.x;   // global float4 idx
                float4 s = ((const float4*)bq)[(bh & (NH - 1)) * (HD / 4) + threadIdx.x];
#pragma unroll 16
                for (int t = 0; t < KTILES; t++) {
                    float4 p = ((const float4*)g_qpart[t])[i];
                    s.x += p.x; s.y += p.y; s.z += p.z; s.w += p.w;
                }
                s.x *= LOG2E; s.y *= LOG2E; s.z *= LOG2E; s.w *= LOG2E;
                ((float4*)g_q)[i] = s;
            }
            __syncthreads();
            __threadfence();                 // release q row
            if (threadIdx.x == 0) atomicExch(&g_qready[bh], 1);
            continue;                        // next queue grab
        }

        // ---------------- attention item ----------------
        const int idx   = item - NBH;
        const int split = idx & (NSPLIT - 1);
        const int bh    = idx >> LOG2SPL;    // b*NH + h
        const int h     = bh & (NH - 1);
        const int b     = bh >> 5;

        // wait for this bh's q row (producer is a resident block)
        if (threadIdx.x == 0) {
            while (atomicAdd(&g_qready[bh], 0) == 0) __nanosleep(64);
        }
        __syncthreads();
        __threadfence();                     // acquire q row

        // q fragment (already log2e-scaled): lane holds q[lane*4..+3]
        const float4 q4 = *(const float4*)&g_q[bh * HD + lane * 4];

        float  m = -1e30f, l = 0.0f;
        float4 acc = make_float4(0.f, 0.f, 0.f, 0.f);

        // warp handles token pairs (s, s+1), pair stride 2*NWARP tokens
        const int s0 = split * TOKS + warp * 2;
        size_t base = (((size_t)b * SEQ + s0) * NH + h) * 64;
        const size_t PSTRIDE = (size_t)(2 * NWARP) * TOKF4;

        float4 kb[DEPTH][2], vb[DEPTH][2];
#pragma unroll
        for (int i = 0; i < DEPTH; i++) {
            kb[i][0] = __ldcs(&kv4[base + lane]);
            vb[i][0] = __ldcs(&kv4[base + 32 + lane]);
            kb[i][1] = __ldcs(&kv4[base + TOKF4 + lane]);
            vb[i][1] = __ldcs(&kv4[base + TOKF4 + 32 + lane]);
            base += PSTRIDE;
        }

#pragma unroll
        for (int p = 0; p < NPAIR; p++) {
            const int slot = p % DEPTH;
            float4 kc0 = kb[slot][0], vc0 = vb[slot][0];
            float4 kc1 = kb[slot][1], vc1 = vb[slot][1];
            if (p + DEPTH < NPAIR) {
                kb[slot][0] = __ldcs(&kv4[base + lane]);
                vb[slot][0] = __ldcs(&kv4[base + 32 + lane]);
                kb[slot][1] = __ldcs(&kv4[base + TOKF4 + lane]);
                vb[slot][1] = __ldcs(&kv4[base + TOKF4 + 32 + lane]);
                base += PSTRIDE;
            }
            float sc0 = kc0.x * q4.x + kc0.y * q4.y + kc0.z * q4.z + kc0.w * q4.w;
            float sc1 = kc1.x * q4.x + kc1.y * q4.y + kc1.z * q4.z + kc1.w * q4.w;
#pragma unroll
            for (int o = 16; o > 0; o >>= 1) {
                sc0 += __shfl_xor_sync(0xffffffffu, sc0, o);
                sc1 += __shfl_xor_sync(0xffffffffu, sc1, o);
            }
            float nm    = fmaxf(m, fmaxf(sc0, sc1));
            float scale = exp2f(m - nm);
            float p0    = exp2f(sc0 - nm);
            float p1    = exp2f(sc1 - nm);
            m = nm;
            l = l * scale + p0 + p1;
            acc.x = acc.x * scale + p0 * vc0.x + p1 * vc1.x;
            acc.y = acc.y * scale + p0 * vc0.y + p1 * vc1.y;
            acc.z = acc.z * scale + p0 * vc0.z + p1 * vc1.z;
            acc.w = acc.w * scale + p0 * vc0.w + p1 * vc1.w;
        }

        // merge the NWARP per-warp partial softmaxes
        s_acc[warp][lane * 4 + 0] = acc.x;
        s_acc[warp][lane * 4 + 1] = acc.y;
        s_acc[warp][lane * 4 + 2] = acc.z;
        s_acc[warp][lane * 4 + 3] = acc.w;
        if (lane == 0) { s_m[warp] = m; s_l[warp] = l; }
        __syncthreads();

        float M = -1e30f;
#pragma unroll
        for (int w = 0; w < NWARP; w++) M = fmaxf(M, s_m[w]);
        float L = 0.0f;
#pragma unroll
        for (int w = 0; w < NWARP; w++) L += exp2f(s_m[w] - M) * s_l[w];

        const int d = threadIdx.x;
        if (d < HD) {
            float a = 0.0f;
#pragma unroll
            for (int w = 0; w < NWARP; w++) a += exp2f(s_m[w] - M) * s_acc[w][d];
            g_pacc[(bh * NSPLIT + split) * HD + d] = a;
        }
        if (threadIdx.x == 0)
            g_pml[bh * NSPLIT + split] = make_float2(M, L);

        // ---- completion protocol: release our partials, count splits ----
        __threadfence();                     // release (all writers fence)
        __syncthreads();
        if (threadIdx.x == 0)
            s_last = (atomicAdd(&g_done[bh], 1) == NSPLIT - 1);
        __syncthreads();

        if (s_last) {
            // we finished the last split of this bh: combine (L2-hot reads)
            __threadfence();                 // acquire
            if (threadIdx.x < HD) {
                float2 ml[NSPLIT];
#pragma unroll
                for (int i = 0; i < NSPLIT; i++)
                    ml[i] = __ldg(&g_pml[bh * NSPLIT + i]);
                float Mg = -1e30f;
#pragma unroll
                for (int i = 0; i < NSPLIT; i++) Mg = fmaxf(Mg, ml[i].x);
                float Lg = 0.0f;
#pragma unroll
                for (int i = 0; i < NSPLIT; i++)
                    Lg += exp2f(ml[i].x - Mg) * ml[i].y;

                float pa[NSPLIT];
#pragma unroll
                for (int i = 0; i < NSPLIT; i++)
                    pa[i] = __ldg(&g_pacc[(bh * NSPLIT + i) * HD + threadIdx.x]);
                float a = 0.0f;
#pragma unroll
                for (int i = 0; i < NSPLIT; i++)
                    a += exp2f(ml[i].x - Mg) * pa[i];

                out[bh * HD + threadIdx.x] = a / Lg;
            }
        }
        __syncthreads();   // protect s_item / s_* / s_last reuse across items
    }
}

// ---------------------------------------------------------------------------
extern "C" void kernel_launch(void* const* d_in, const int* in_sizes, int n_in,
                              void* d_out, int out_size) {
    const float* hq = (const float*)d_in[0];   // (8, 1536)
    const float* kv = (const float*)d_in[1];   // (8, 4096, 32, 256)
    const float* W  = (const float*)d_in[2];   // (1536, 4096)
    const float* bq = (const float*)d_in[3];   // (4096,)
    float* out = (float*)d_out;                // (8, 4096)

    qgemm_kernel<<<dim3(NQ / 4 / 128, KTILES), 128>>>(hq, W);
    attn_partial_kernel<<<GRID_AT, NWARP * 32>>>(kv, bq, out);
}

// round 16
// speedup vs baseline: 1.0983x; 1.0198x over previous
#include <cuda_runtime.h>

#define NH      32
#define HD      128
#define QLR     1536
#define BSZ     8
#define SEQ     4096
#define NQ      (NH*HD)            // 4096 q columns
#define NCOL4   (NQ/4)             // 1024 float4 columns per batch row
#define NBH     (BSZ*NH)           // 256 bh rows
#define NSPLIT  16
#define LOG2SPL 4
#define TOKS    (SEQ/NSPLIT)       // 256 tokens per work item
#define NWARP   8                  // warps per attention block
#define NPAIR   (TOKS/(2*NWARP))   // 16 pair-iterations per warp
#define NATT    (NBH*NSPLIT)       // 4096 attention work items
#define GRID_AT (148*3)            // persistent grid (3 blocks/SM, all resident)
#define KTILES  96
#define KCHUNK  (QLR/KTILES)       // 16
#define NREG    4                  // column regions (256 col4 each)
#define RCOL4   (NCOL4/NREG)       // 256 col4 per region
#define NGEMM   (NREG*KTILES)      // 384 gemm items
#define NITEMS_TOT (NGEMM + NBH + NATT)   // 4736
#define LOG2E   1.4426950408889634f
#define TOKF4   ((size_t)NH * 64)  // float4 stride between consecutive tokens
#define DEPTH   3                  // prefetch depth in token-pairs

// Scratch (device globals: no allocation in kernel_launch; zero-init at load,
// self-reset by the last exiting block each launch -> graph-replay safe)
__device__ float  g_qpart[KTILES][BSZ*NQ];      // split-K GEMM partials (12 MB)
__device__ float  g_q[BSZ*NQ];                  // q = h@W + b (log2e-scaled)
__device__ float  g_pacc[NBH*NSPLIT*HD];        // split-KV weighted-V partials
__device__ float2 g_pml[NBH*NSPLIT];            // (max, sumexp) per split
__device__ int    g_work;                        // work-queue counter
__device__ int    g_done[NBH];                   // per-bh completed-split counters
__device__ int    g_qready[NBH];                 // per-bh q-row readiness flags
__device__ int    g_gdone[NREG];                 // per-region gemm-tile counters
__device__ int    g_exit;                        // block exit counter

// ---------------------------------------------------------------------------
// Single persistent kernel. Queue item map:
//   [0, NGEMM)            gemm item  = (region, ktile): 256 col4 x 16 k
//   [NGEMM, NGEMM+NBH)    q-reduce item = bh row (spins on its column region)
//   [NGEMM+NBH, total)    attention split item (spins on g_qready[bh])
// Dependency chain gemm -> q-reduce -> attention matches queue order and is
// acyclic; all producers are resident blocks -> every spin is bounded.
// ---------------------------------------------------------------------------
__global__ void __launch_bounds__(NWARP * 32, 3)
fused_kernel(const float* __restrict__ kv,
             const float* __restrict__ hq,
             const float* __restrict__ W,
             const float* __restrict__ bq,
             float* __restrict__ out) {
    __shared__ int   s_item;
    __shared__ int   s_last;
    __shared__ float s_acc[NWARP][HD];      // also reused as hq slice in gemm
    __shared__ float s_m[NWARP], s_l[NWARP];

    const int tid  = threadIdx.x;
    const int warp = tid >> 5;
    const int lane = tid & 31;
    const float4* kv4 = (const float4*)kv;
    const float4* W4  = (const float4*)W;

    for (;;) {
        if (tid == 0) s_item = atomicAdd(&g_work, 1);
        __syncthreads();
        const int item = s_item;
        if (item >= NITEMS_TOT) break;

        // ---------------- gemm item ----------------
        if (item < NGEMM) {
            const int region = item / KTILES;
            const int ktile  = item % KTILES;
            const int k0     = ktile * KCHUNK;

            float* sh_h = &s_acc[0][0];      // BSZ*KCHUNK = 128 floats
            if (tid < BSZ * KCHUNK)
                sh_h[tid] = hq[(tid / KCHUNK) * QLR + k0 + (tid % KCHUNK)];
            __syncthreads();

            const int col4 = region * RCOL4 + tid;   // 256 col4 per item
            float4 acc[BSZ];
#pragma unroll
            for (int b = 0; b < BSZ; b++) acc[b] = make_float4(0.f, 0.f, 0.f, 0.f);
#pragma unroll
            for (int k = 0; k < KCHUNK; k++) {
                float4 w = __ldcs(&W4[(size_t)(k0 + k) * NCOL4 + col4]);
#pragma unroll
                for (int b = 0; b < BSZ; b++) {
                    float s = sh_h[b * KCHUNK + k];
                    acc[b].x += w.x * s; acc[b].y += w.y * s;
                    acc[b].z += w.z * s; acc[b].w += w.w * s;
                }
            }
#pragma unroll
            for (int b = 0; b < BSZ; b++)
                ((float4*)&g_qpart[ktile][b * NQ])[col4] = acc[b];

            __threadfence();                 // release partials
            __syncthreads();
            if (tid == 0) atomicAdd(&g_gdone[region], 1);
            __syncthreads();                 // protect sh_h reuse
            continue;
        }

        // ---------------- q-reduce item ----------------
        if (item < NGEMM + NBH) {
            const int bh     = item - NGEMM;
            const int h      = bh & (NH - 1);
            const int region = h >> 3;       // h*32 col4 / 256  -> 0..3
            if (tid == 0) {
                while (atomicAdd(&g_gdone[region], 0) < KTILES) __nanosleep(64);
            }
            __syncthreads();
            __threadfence();                 // acquire partials

            if (tid < HD / 4) {
                const int i = bh * (HD / 4) + tid;   // global col4 index
                float4 s = ((const float4*)bq)[h * (HD / 4) + tid];
#pragma unroll 16
                for (int t = 0; t < KTILES; t++) {
                    float4 p = ((const float4*)g_qpart[t])[i];
                    s.x += p.x; s.y += p.y; s.z += p.z; s.w += p.w;
                }
                s.x *= LOG2E; s.y *= LOG2E; s.z *= LOG2E; s.w *= LOG2E;
                ((float4*)g_q)[i] = s;
            }
            __syncthreads();
            __threadfence();                 // release q row
            if (tid == 0) atomicExch(&g_qready[bh], 1);
            continue;
        }

        // ---------------- attention item ----------------
        const int idx   = item - NGEMM - NBH;
        const int split = idx & (NSPLIT - 1);
        const int bh    = idx >> LOG2SPL;    // b*NH + h
        const int h     = bh & (NH - 1);
        const int b     = bh >> 5;

        // issue kv prefetch BEFORE waiting for q (loads are q-independent)
        const int s0 = split * TOKS + warp * 2;
        size_t base = (((size_t)b * SEQ + s0) * NH + h) * 64;
        const size_t PSTRIDE = (size_t)(2 * NWARP) * TOKF4;

        float4 kb[DEPTH][2], vb[DEPTH][2];
#pragma unroll
        for (int i = 0; i < DEPTH; i++) {
            kb[i][0] = __ldcs(&kv4[base + lane]);
            vb[i][0] = __ldcs(&kv4[base + 32 + lane]);
            kb[i][1] = __ldcs(&kv4[base + TOKF4 + lane]);
            vb[i][1] = __ldcs(&kv4[base + TOKF4 + 32 + lane]);
            base += PSTRIDE;
        }

        // wait for this bh's q row (producer is a resident block)
        if (tid == 0) {
            while (atomicAdd(&g_qready[bh], 0) == 0) __nanosleep(64);
        }
        __syncthreads();
        __threadfence();                     // acquire q row

        const float4 q4 = *(const float4*)&g_q[bh * HD + lane * 4];

        float  m = -1e30f, l = 0.0f;
        float4 acc = make_float4(0.f, 0.f, 0.f, 0.f);

#pragma unroll
        for (int p = 0; p < NPAIR; p++) {
            const int slot = p % DEPTH;
            float4 kc0 = kb[slot][0], vc0 = vb[slot][0];
            float4 kc1 = kb[slot][1], vc1 = vb[slot][1];
            if (p + DEPTH < NPAIR) {
                kb[slot][0] = __ldcs(&kv4[base + lane]);
                vb[slot][0] = __ldcs(&kv4[base + 32 + lane]);
                kb[slot][1] = __ldcs(&kv4[base + TOKF4 + lane]);
                vb[slot][1] = __ldcs(&kv4[base + TOKF4 + 32 + lane]);
                base += PSTRIDE;
            }
            float sc0 = kc0.x * q4.x + kc0.y * q4.y + kc0.z * q4.z + kc0.w * q4.w;
            float sc1 = kc1.x * q4.x + kc1.y * q4.y + kc1.z * q4.z + kc1.w * q4.w;
#pragma unroll
            for (int o = 16; o > 0; o >>= 1) {
                sc0 += __shfl_xor_sync(0xffffffffu, sc0, o);
                sc1 += __shfl_xor_sync(0xffffffffu, sc1, o);
            }
            float nm    = fmaxf(m, fmaxf(sc0, sc1));
            float scale = exp2f(m - nm);
            float p0    = exp2f(sc0 - nm);
            float p1    = exp2f(sc1 - nm);
            m = nm;
            l = l * scale + p0 + p1;
            acc.x = acc.x * scale + p0 * vc0.x + p1 * vc1.x;
            acc.y = acc.y * scale + p0 * vc0.y + p1 * vc1.y;
            acc.z = acc.z * scale + p0 * vc0.z + p1 * vc1.z;
            acc.w = acc.w * scale + p0 * vc0.w + p1 * vc1.w;
        }

        // merge the NWARP per-warp partial softmaxes
        s_acc[warp][lane * 4 + 0] = acc.x;
        s_acc[warp][lane * 4 + 1] = acc.y;
        s_acc[warp][lane * 4 + 2] = acc.z;
        s_acc[warp][lane * 4 + 3] = acc.w;
        if (lane == 0) { s_m[warp] = m; s_l[warp] = l; }
        __syncthreads();

        float M = -1e30f;
#pragma unroll
        for (int w = 0; w < NWARP; w++) M = fmaxf(M, s_m[w]);
        float L = 0.0f;
#pragma unroll
        for (int w = 0; w < NWARP; w++) L += exp2f(s_m[w] - M) * s_l[w];

        if (tid < HD) {
            float a = 0.0f;
#pragma unroll
            for (int w = 0; w < NWARP; w++) a += exp2f(s_m[w] - M) * s_acc[w][tid];
            g_pacc[(bh * NSPLIT + split) * HD + tid] = a;
        }
        if (tid == 0)
            g_pml[bh * NSPLIT + split] = make_float2(M, L);

        // ---- completion protocol: release our partials, count splits ----
        __threadfence();                     // release (all writers fence)
        __syncthreads();
        if (tid == 0)
            s_last = (atomicAdd(&g_done[bh], 1) == NSPLIT - 1);
        __syncthreads();

        if (s_last) {
            __threadfence();                 // acquire
            if (tid < HD) {
                float2 ml[NSPLIT];
#pragma unroll
                for (int i = 0; i < NSPLIT; i++)
                    ml[i] = __ldg(&g_pml[bh * NSPLIT + i]);
                float Mg = -1e30f;
#pragma unroll
                for (int i = 0; i < NSPLIT; i++) Mg = fmaxf(Mg, ml[i].x);
                float Lg = 0.0f;
#pragma unroll
                for (int i = 0; i < NSPLIT; i++)
                    Lg += exp2f(ml[i].x - Mg) * ml[i].y;

                float pa[NSPLIT];
#pragma unroll
                for (int i = 0; i < NSPLIT; i++)
                    pa[i] = __ldg(&g_pacc[(bh * NSPLIT + i) * HD + tid]);
                float a = 0.0f;
#pragma unroll
                for (int i = 0; i < NSPLIT; i++)
                    a += exp2f(ml[i].x - Mg) * pa[i];

                out[bh * HD + tid] = a / Lg;
            }
        }
        __syncthreads();   // protect s_item / s_* reuse across items
    }

    // ---- exit protocol: last block resets all counters for next replay ----
    __threadfence();
    __syncthreads();
    if (tid == 0) s_item = atomicAdd(&g_exit, 1);
    __syncthreads();
    if (s_item == GRID_AT - 1) {
        for (int i = tid; i < NBH; i += NWARP * 32) {
            g_done[i]   = 0;
            g_qready[i] = 0;
        }
        if (tid < NREG) g_gdone[tid] = 0;
        if (tid == 0) { g_work = 0; g_exit = 0; }
    }
}

// ---------------------------------------------------------------------------
extern "C" void kernel_launch(void* const* d_in, const int* in_sizes, int n_in,
                              void* d_out, int out_size) {
    const float* hq = (const float*)d_in[0];   // (8, 1536)
    const float* kv = (const float*)d_in[1];   // (8, 4096, 32, 256)
    const float* W  = (const float*)d_in[2];   // (1536, 4096)
    const float* bq = (const float*)d_in[3];   // (4096,)
    float* out = (float*)d_out;                // (8, 4096)

    fused_kernel<<<GRID_AT, NWARP * 32>>>(kv, hq, W, bq, out);
}